// round 1
// baseline (speedup 1.0000x reference)
#include <cuda_runtime.h>
#include <math.h>

#define BATCH 2048
#define UNITS 512
#define FEAT 3
#define SEQ 64
#define OUT_NOTES 64
#define ZCOLS (4 * UNITS)

#define BM 128
#define BN 128
#define BUNIT 32
#define BK 16
#define AS_LD (BM + 4)

// Persistent scratch (no allocations allowed): ping-pong LSTM state + fed-back prediction.
__device__ float g_h[2][BATCH * UNITS];
__device__ float g_c[2][BATCH * UNITS];
__device__ float g_pred[BATCH * FEAT];

__global__ void zero_hc_kernel() {
    const int n = BATCH * UNITS;
    for (int i = blockIdx.x * blockDim.x + threadIdx.x; i < n; i += gridDim.x * blockDim.x) {
        g_h[0][i] = 0.f;
        g_c[0][i] = 0.f;
    }
}

__device__ __forceinline__ float sigf(float x) { return 1.f / (1.f + expf(-x)); }

// Fused LSTM step: z = x@Wk + h@Wr + bias; gates; (h,c) update.
// CTA tile: 128 batch rows x 32 units (=> 128 z-columns, 4 gates interleaved unit-major).
__global__ __launch_bounds__(256, 2)
void lstm_step_kernel(const float* __restrict__ x, int x_stride,
                      const float* __restrict__ wk,     // [3, 2048]
                      const float* __restrict__ wr,     // [512, 2048]
                      const float* __restrict__ bias,   // [2048]
                      int cur)
{
    __shared__ float As[BK][AS_LD];      // h tile, transposed [k][m]
    __shared__ float Bs[BK][BN];         // rec_kernel tile, cols as (unit*4 + gate)
    __shared__ float xs[BM][4];          // x rows for this batch tile
    __shared__ float kc[FEAT][BN];       // kernel columns (same col order as Bs)
    __shared__ float bc[BN];             // bias columns

    const int tid = threadIdx.x;
    const int m0 = blockIdx.x * BM;
    const int u0 = blockIdx.y * BUNIT;

    const float* __restrict__ h_in = g_h[cur];
    const float* __restrict__ c_in = g_c[cur];
    float* __restrict__ h_out = g_h[cur ^ 1];
    float* __restrict__ c_out = g_c[cur ^ 1];

    // One-time per-CTA loads of x rows and kernel/bias columns
    if (tid < BM) {
        const float* xr = x + (size_t)(m0 + tid) * x_stride;
        xs[tid][0] = xr[0];
        xs[tid][1] = xr[1];
        xs[tid][2] = xr[2];
    } else {
        const int c = tid - BM;               // smem column index = unit*4 + gate
        const int ul = c >> 2, g = c & 3;
        const int col = g * UNITS + u0 + ul;  // global z column
        bc[c] = bias[col];
        kc[0][c] = wk[col];
        kc[1][c] = wk[ZCOLS + col];
        kc[2][c] = wk[2 * ZCOLS + col];
    }

    // A-tile load indices (float4, coalesced): thread -> (row, k-quad)
    const int a_m = tid >> 2;                 // 0..63
    const int a_k = (tid & 3) << 2;           // 0,4,8,12
    // B-tile load indices (coalesced gate-major in gmem, stored unit-major in smem)
    const int b_k = tid >> 7;                 // 0..1
    const int b_c = tid & 127;                // gate-major: g = b_c>>5, ul = b_c&31
    const int b_cs = ((b_c & 31) << 2) | (b_c >> 5);
    const size_t b_col = (size_t)(b_c >> 5) * UNITS + u0 + (b_c & 31);

    // Compute microtile mapping: rows {r4..r4+3, 64+r4..}, cols {c4..c4+3, 64+c4..}
    const int r4 = (tid >> 4) << 2;
    const int c4 = (tid & 15) << 2;

    float acc[8][8];
#pragma unroll
    for (int i = 0; i < 8; i++)
#pragma unroll
        for (int j = 0; j < 8; j++) acc[i][j] = 0.f;

    // Prefetch first k-chunk into registers
    float4 pa0 = *(const float4*)&h_in[(size_t)(m0 + a_m) * UNITS + a_k];
    float4 pa1 = *(const float4*)&h_in[(size_t)(m0 + a_m + 64) * UNITS + a_k];
    float pb[8];
#pragma unroll
    for (int r = 0; r < 8; r++)
        pb[r] = wr[(size_t)(b_k + 2 * r) * ZCOLS + b_col];

    for (int k0 = 0; k0 < UNITS; k0 += BK) {
        // Commit prefetched chunk to smem
        As[a_k + 0][a_m] = pa0.x;
        As[a_k + 1][a_m] = pa0.y;
        As[a_k + 2][a_m] = pa0.z;
        As[a_k + 3][a_m] = pa0.w;
        As[a_k + 0][a_m + 64] = pa1.x;
        As[a_k + 1][a_m + 64] = pa1.y;
        As[a_k + 2][a_m + 64] = pa1.z;
        As[a_k + 3][a_m + 64] = pa1.w;
#pragma unroll
        for (int r = 0; r < 8; r++)
            Bs[b_k + 2 * r][b_cs] = pb[r];
        __syncthreads();

        // Prefetch next chunk while computing this one
        const int k1 = k0 + BK;
        if (k1 < UNITS) {
            pa0 = *(const float4*)&h_in[(size_t)(m0 + a_m) * UNITS + k1 + a_k];
            pa1 = *(const float4*)&h_in[(size_t)(m0 + a_m + 64) * UNITS + k1 + a_k];
#pragma unroll
            for (int r = 0; r < 8; r++)
                pb[r] = wr[(size_t)(k1 + b_k + 2 * r) * ZCOLS + b_col];
        }

#pragma unroll
        for (int kk = 0; kk < BK; kk++) {
            const float4 av0 = *(const float4*)&As[kk][r4];
            const float4 av1 = *(const float4*)&As[kk][r4 + 64];
            const float4 bv0 = *(const float4*)&Bs[kk][c4];
            const float4 bv1 = *(const float4*)&Bs[kk][c4 + 64];
            const float a[8] = {av0.x, av0.y, av0.z, av0.w, av1.x, av1.y, av1.z, av1.w};
            const float b[8] = {bv0.x, bv0.y, bv0.z, bv0.w, bv1.x, bv1.y, bv1.z, bv1.w};
#pragma unroll
            for (int i = 0; i < 8; i++)
#pragma unroll
                for (int j = 0; j < 8; j++)
                    acc[i][j] = fmaf(a[i], b[j], acc[i][j]);
        }
        __syncthreads();
    }

    // Epilogue: add x@Wk + bias, apply gates, update state. All in registers.
#pragma unroll
    for (int rh = 0; rh < 2; rh++) {
#pragma unroll
        for (int ii = 0; ii < 4; ii++) {
            const int lrow = rh * 64 + r4 + ii;
            const int brow = m0 + lrow;
            const float x0 = xs[lrow][0];
            const float x1 = xs[lrow][1];
            const float x2 = xs[lrow][2];
            const int i = rh * 4 + ii;
#pragma unroll
            for (int ch = 0; ch < 2; ch++) {
                float z[4];
#pragma unroll
                for (int g = 0; g < 4; g++) {
                    const int j = ch * 4 + g;
                    const int c = ch * 64 + c4 + g;
                    z[g] = acc[i][j] + bc[c]
                         + x0 * kc[0][c] + x1 * kc[1][c] + x2 * kc[2][c];
                }
                const int u = u0 + ch * 16 + (c4 >> 2);
                const size_t idx = (size_t)brow * UNITS + u;
                const float ig = sigf(z[0]);
                const float fg = sigf(z[1]);
                const float gg = tanhf(z[2]);
                const float og = sigf(z[3]);
                const float cn = fmaf(fg, c_in[idx], ig * gg);
                c_out[idx] = cn;
                h_out[idx] = og * tanhf(cn);
            }
        }
    }
}

// pred = h @ dense_w + dense_b  (one warp per batch row). Writes output slice
// and g_pred (the next autoregressive input).
__global__ void dense_kernel(int cur, const float* __restrict__ dw,
                             const float* __restrict__ db,
                             float* __restrict__ out_t)
{
    const int gwarp = (blockIdx.x * blockDim.x + threadIdx.x) >> 5;
    const int lane = threadIdx.x & 31;
    if (gwarp >= BATCH) return;
    const float* __restrict__ h = g_h[cur] + (size_t)gwarp * UNITS;
    float s0 = 0.f, s1 = 0.f, s2 = 0.f;
    for (int u = lane; u < UNITS; u += 32) {
        const float hv = h[u];
        s0 = fmaf(hv, dw[u * 3 + 0], s0);
        s1 = fmaf(hv, dw[u * 3 + 1], s1);
        s2 = fmaf(hv, dw[u * 3 + 2], s2);
    }
#pragma unroll
    for (int o = 16; o; o >>= 1) {
        s0 += __shfl_down_sync(0xffffffffu, s0, o);
        s1 += __shfl_down_sync(0xffffffffu, s1, o);
        s2 += __shfl_down_sync(0xffffffffu, s2, o);
    }
    if (lane == 0) {
        const float p0 = s0 + db[0];
        const float p1 = s1 + db[1];
        const float p2 = s2 + db[2];
        out_t[gwarp * 3 + 0] = p0;
        out_t[gwarp * 3 + 1] = p1;
        out_t[gwarp * 3 + 2] = p2;
        g_pred[gwarp * 3 + 0] = p0;
        g_pred[gwarp * 3 + 1] = p1;
        g_pred[gwarp * 3 + 2] = p2;
    }
}

extern "C" void kernel_launch(void* const* d_in, const int* in_sizes, int n_in,
                              void* d_out, int out_size) {
    const float* inputs = (const float*)d_in[0];  // [B, S, F]
    const float* wk     = (const float*)d_in[1];  // [F, 4U]
    const float* wr     = (const float*)d_in[2];  // [U, 4U]
    const float* bias   = (const float*)d_in[3];  // [4U]
    const float* dw     = (const float*)d_in[4];  // [U, F]
    const float* db     = (const float*)d_in[5];  // [F]
    float* out = (float*)d_out;                   // [OUT_NOTES, B, F]

    float* pred_ptr = nullptr;
    cudaGetSymbolAddress((void**)&pred_ptr, g_pred);

    zero_hc_kernel<<<256, 256>>>();

    const dim3 grid(BATCH / BM, UNITS / BUNIT);
    int cur = 0;
    // Warmup: 64 steps over the input sequence
    for (int t = 0; t < SEQ; t++) {
        lstm_step_kernel<<<grid, 256>>>(inputs + t * FEAT, SEQ * FEAT, wk, wr, bias, cur);
        cur ^= 1;
    }
    // pred0
    dense_kernel<<<BATCH / 8, 256>>>(cur, dw, db, out);
    // Autoregressive rollout: 63 steps feeding pred back in
    for (int t = 1; t < OUT_NOTES; t++) {
        lstm_step_kernel<<<grid, 256>>>(pred_ptr, FEAT, wk, wr, bias, cur);
        cur ^= 1;
        dense_kernel<<<BATCH / 8, 256>>>(cur, dw, db, out + (size_t)t * BATCH * FEAT);
    }
}

// round 2
// speedup vs baseline: 1.0010x; 1.0010x over previous
#include <cuda_runtime.h>
#include <math.h>

#define BATCH 2048
#define UNITS 512
#define FEAT 3
#define SEQ 64
#define OUT_NOTES 64
#define ZCOLS (4 * UNITS)

#define BM 128
#define BN 128
#define BUNIT 32
#define BK 16
#define AS_LD (BM + 4)

// Persistent scratch (no allocations allowed): ping-pong LSTM state + fed-back prediction.
__device__ float g_h[2][BATCH * UNITS];
__device__ float g_c[2][BATCH * UNITS];
__device__ float g_pred[BATCH * FEAT];

__global__ void zero_hc_kernel() {
    const int n = BATCH * UNITS;
    for (int i = blockIdx.x * blockDim.x + threadIdx.x; i < n; i += gridDim.x * blockDim.x) {
        g_h[0][i] = 0.f;
        g_c[0][i] = 0.f;
    }
}

__device__ __forceinline__ float sigf(float x) { return 1.f / (1.f + expf(-x)); }

// Fused LSTM step: z = x@Wk + h@Wr + bias; gates; (h,c) update.
// CTA tile: 128 batch rows x 32 units (=> 128 z-columns, 4 gates interleaved unit-major).
__global__ __launch_bounds__(256, 2)
void lstm_step_kernel(const float* __restrict__ x, int x_stride,
                      const float* __restrict__ wk,     // [3, 2048]
                      const float* __restrict__ wr,     // [512, 2048]
                      const float* __restrict__ bias,   // [2048]
                      int cur)
{
    __shared__ float As[BK][AS_LD];      // h tile, transposed [k][m]
    __shared__ float Bs[BK][BN];         // rec_kernel tile, cols as (unit*4 + gate)
    __shared__ float xs[BM][4];          // x rows for this batch tile
    __shared__ float kc[FEAT][BN];       // kernel columns (same col order as Bs)
    __shared__ float bc[BN];             // bias columns

    const int tid = threadIdx.x;
    const int m0 = blockIdx.x * BM;
    const int u0 = blockIdx.y * BUNIT;

    const float* __restrict__ h_in = g_h[cur];
    const float* __restrict__ c_in = g_c[cur];
    float* __restrict__ h_out = g_h[cur ^ 1];
    float* __restrict__ c_out = g_c[cur ^ 1];

    // One-time per-CTA loads of x rows and kernel/bias columns
    if (tid < BM) {
        const float* xr = x + (size_t)(m0 + tid) * x_stride;
        xs[tid][0] = xr[0];
        xs[tid][1] = xr[1];
        xs[tid][2] = xr[2];
    } else {
        const int c = tid - BM;               // smem column index = unit*4 + gate
        const int ul = c >> 2, g = c & 3;
        const int col = g * UNITS + u0 + ul;  // global z column
        bc[c] = bias[col];
        kc[0][c] = wk[col];
        kc[1][c] = wk[ZCOLS + col];
        kc[2][c] = wk[2 * ZCOLS + col];
    }

    // A-tile load indices (float4, coalesced): thread -> (row, k-quad)
    const int a_m = tid >> 2;                 // 0..63
    const int a_k = (tid & 3) << 2;           // 0,4,8,12
    // B-tile load indices (coalesced gate-major in gmem, stored unit-major in smem)
    const int b_k = tid >> 7;                 // 0..1
    const int b_c = tid & 127;                // gate-major: g = b_c>>5, ul = b_c&31
    const int b_cs = ((b_c & 31) << 2) | (b_c >> 5);
    const size_t b_col = (size_t)(b_c >> 5) * UNITS + u0 + (b_c & 31);

    // Compute microtile mapping: rows {r4..r4+3, 64+r4..}, cols {c4..c4+3, 64+c4..}
    const int r4 = (tid >> 4) << 2;
    const int c4 = (tid & 15) << 2;

    float acc[8][8];
#pragma unroll
    for (int i = 0; i < 8; i++)
#pragma unroll
        for (int j = 0; j < 8; j++) acc[i][j] = 0.f;

    // Prefetch first k-chunk into registers
    float4 pa0 = *(const float4*)&h_in[(size_t)(m0 + a_m) * UNITS + a_k];
    float4 pa1 = *(const float4*)&h_in[(size_t)(m0 + a_m + 64) * UNITS + a_k];
    float pb[8];
#pragma unroll
    for (int r = 0; r < 8; r++)
        pb[r] = wr[(size_t)(b_k + 2 * r) * ZCOLS + b_col];

    for (int k0 = 0; k0 < UNITS; k0 += BK) {
        // Commit prefetched chunk to smem
        As[a_k + 0][a_m] = pa0.x;
        As[a_k + 1][a_m] = pa0.y;
        As[a_k + 2][a_m] = pa0.z;
        As[a_k + 3][a_m] = pa0.w;
        As[a_k + 0][a_m + 64] = pa1.x;
        As[a_k + 1][a_m + 64] = pa1.y;
        As[a_k + 2][a_m + 64] = pa1.z;
        As[a_k + 3][a_m + 64] = pa1.w;
#pragma unroll
        for (int r = 0; r < 8; r++)
            Bs[b_k + 2 * r][b_cs] = pb[r];
        __syncthreads();

        // Prefetch next chunk while computing this one
        const int k1 = k0 + BK;
        if (k1 < UNITS) {
            pa0 = *(const float4*)&h_in[(size_t)(m0 + a_m) * UNITS + k1 + a_k];
            pa1 = *(const float4*)&h_in[(size_t)(m0 + a_m + 64) * UNITS + k1 + a_k];
#pragma unroll
            for (int r = 0; r < 8; r++)
                pb[r] = wr[(size_t)(k1 + b_k + 2 * r) * ZCOLS + b_col];
        }

#pragma unroll
        for (int kk = 0; kk < BK; kk++) {
            const float4 av0 = *(const float4*)&As[kk][r4];
            const float4 av1 = *(const float4*)&As[kk][r4 + 64];
            const float4 bv0 = *(const float4*)&Bs[kk][c4];
            const float4 bv1 = *(const float4*)&Bs[kk][c4 + 64];
            const float a[8] = {av0.x, av0.y, av0.z, av0.w, av1.x, av1.y, av1.z, av1.w};
            const float b[8] = {bv0.x, bv0.y, bv0.z, bv0.w, bv1.x, bv1.y, bv1.z, bv1.w};
#pragma unroll
            for (int i = 0; i < 8; i++)
#pragma unroll
                for (int j = 0; j < 8; j++)
                    acc[i][j] = fmaf(a[i], b[j], acc[i][j]);
        }
        __syncthreads();
    }

    // Epilogue: add x@Wk + bias, apply gates, update state. All in registers.
#pragma unroll
    for (int rh = 0; rh < 2; rh++) {
#pragma unroll
        for (int ii = 0; ii < 4; ii++) {
            const int lrow = rh * 64 + r4 + ii;
            const int brow = m0 + lrow;
            const float x0 = xs[lrow][0];
            const float x1 = xs[lrow][1];
            const float x2 = xs[lrow][2];
            const int i = rh * 4 + ii;
#pragma unroll
            for (int ch = 0; ch < 2; ch++) {
                float z[4];
#pragma unroll
                for (int g = 0; g < 4; g++) {
                    const int j = ch * 4 + g;
                    const int c = ch * 64 + c4 + g;
                    z[g] = acc[i][j] + bc[c]
                         + x0 * kc[0][c] + x1 * kc[1][c] + x2 * kc[2][c];
                }
                const int u = u0 + ch * 16 + (c4 >> 2);
                const size_t idx = (size_t)brow * UNITS + u;
                const float ig = sigf(z[0]);
                const float fg = sigf(z[1]);
                const float gg = tanhf(z[2]);
                const float og = sigf(z[3]);
                const float cn = fmaf(fg, c_in[idx], ig * gg);
                c_out[idx] = cn;
                h_out[idx] = og * tanhf(cn);
            }
        }
    }
}

// pred = h @ dense_w + dense_b  (one warp per batch row). Writes output slice
// and g_pred (the next autoregressive input).
__global__ void dense_kernel(int cur, const float* __restrict__ dw,
                             const float* __restrict__ db,
                             float* __restrict__ out_t)
{
    const int gwarp = (blockIdx.x * blockDim.x + threadIdx.x) >> 5;
    const int lane = threadIdx.x & 31;
    if (gwarp >= BATCH) return;
    const float* __restrict__ h = g_h[cur] + (size_t)gwarp * UNITS;
    float s0 = 0.f, s1 = 0.f, s2 = 0.f;
    for (int u = lane; u < UNITS; u += 32) {
        const float hv = h[u];
        s0 = fmaf(hv, dw[u * 3 + 0], s0);
        s1 = fmaf(hv, dw[u * 3 + 1], s1);
        s2 = fmaf(hv, dw[u * 3 + 2], s2);
    }
#pragma unroll
    for (int o = 16; o; o >>= 1) {
        s0 += __shfl_down_sync(0xffffffffu, s0, o);
        s1 += __shfl_down_sync(0xffffffffu, s1, o);
        s2 += __shfl_down_sync(0xffffffffu, s2, o);
    }
    if (lane == 0) {
        const float p0 = s0 + db[0];
        const float p1 = s1 + db[1];
        const float p2 = s2 + db[2];
        out_t[gwarp * 3 + 0] = p0;
        out_t[gwarp * 3 + 1] = p1;
        out_t[gwarp * 3 + 2] = p2;
        g_pred[gwarp * 3 + 0] = p0;
        g_pred[gwarp * 3 + 1] = p1;
        g_pred[gwarp * 3 + 2] = p2;
    }
}

extern "C" void kernel_launch(void* const* d_in, const int* in_sizes, int n_in,
                              void* d_out, int out_size) {
    const float* inputs = (const float*)d_in[0];  // [B, S, F]
    const float* wk     = (const float*)d_in[1];  // [F, 4U]
    const float* wr     = (const float*)d_in[2];  // [U, 4U]
    const float* bias   = (const float*)d_in[3];  // [4U]
    const float* dw     = (const float*)d_in[4];  // [U, F]
    const float* db     = (const float*)d_in[5];  // [F]
    float* out = (float*)d_out;                   // [OUT_NOTES, B, F]

    float* pred_ptr = nullptr;
    cudaGetSymbolAddress((void**)&pred_ptr, g_pred);

    zero_hc_kernel<<<256, 256>>>();

    const dim3 grid(BATCH / BM, UNITS / BUNIT);
    int cur = 0;
    // Warmup: 64 steps over the input sequence
    for (int t = 0; t < SEQ; t++) {
        lstm_step_kernel<<<grid, 256>>>(inputs + t * FEAT, SEQ * FEAT, wk, wr, bias, cur);
        cur ^= 1;
    }
    // pred0
    dense_kernel<<<BATCH / 8, 256>>>(cur, dw, db, out);
    // Autoregressive rollout: 63 steps feeding pred back in
    for (int t = 1; t < OUT_NOTES; t++) {
        lstm_step_kernel<<<grid, 256>>>(pred_ptr, FEAT, wk, wr, bias, cur);
        cur ^= 1;
        dense_kernel<<<BATCH / 8, 256>>>(cur, dw, db, out + (size_t)t * BATCH * FEAT);
    }
}